// round 1
// baseline (speedup 1.0000x reference)
#include <cuda_runtime.h>
#include <float.h>

#define N 8192
#define D 128
#define P 4096
#define BM 128
#define BK 32
#define NT (N / BM)   // 64 tiles per dimension
#define SMP (BM + 4)  // padded row stride (132 floats)

// Persistent scratch (allocation-free rule): fully rewritten every launch.
__device__ float g_self[P];
__device__ float g_blkV[NT * NT * 2];
__device__ int   g_blkI[NT * NT * 2];

__device__ __forceinline__ void ins2(float& v1, int& i1, float& v2, int& i2,
                                     float v, int i) {
    if (v > v1) { v2 = v1; i2 = i1; v1 = v; i1 = i; }
    else if (v > v2) { v2 = v; i2 = i; }
}

// Kernel 1: sim_self[p] = dot(x[p], x[p+1]), one warp per p.
__global__ void self_kernel(const float* __restrict__ x) {
    int w = (blockIdx.x * blockDim.x + threadIdx.x) >> 5;
    int lane = threadIdx.x & 31;
    if (w >= P) return;
    const float* a = x + (size_t)w * D;
    const float* b = x + (size_t)(w + 1) * D;
    float s = 0.f;
#pragma unroll
    for (int k = lane; k < D; k += 32) s = fmaf(a[k], b[k], s);
#pragma unroll
    for (int o = 16; o; o >>= 1) s += __shfl_xor_sync(0xffffffffu, s, o);
    if (lane == 0) g_self[w] = s;
}

// Kernel 2: 128x128 Gram tile, FFMA, per-block top-2 of masked (i<j) entries.
__global__ __launch_bounds__(256, 2) void gram_kernel(const float* __restrict__ x) {
    const int bx = blockIdx.x, by = blockIdx.y;   // bx = col tile, by = row tile
    const int bid = by * NT + bx;
    if (bx < by) {
        if (threadIdx.x == 0) {
            g_blkV[bid * 2] = -FLT_MAX; g_blkV[bid * 2 + 1] = -FLT_MAX;
            g_blkI[bid * 2] = -1;       g_blkI[bid * 2 + 1] = -1;
        }
        return;
    }

    __shared__ __align__(16) float As[BK][SMP];  // K-transposed: As[k][row]
    __shared__ __align__(16) float Bs[BK][SMP];

    const int tid = threadIdx.x;
    const int tx = tid & 15, ty = tid >> 4;
    const int rowBase = by * BM, colBase = bx * BM;

    float acc[8][8];
#pragma unroll
    for (int i = 0; i < 8; ++i)
#pragma unroll
        for (int j = 0; j < 8; ++j) acc[i][j] = 0.f;

    const float4* __restrict__ x4 = (const float4*)x;
    const int lrow = tid & 31;          // row within 32-row group (distinct per warp)
    const int k4 = (tid >> 5) << 2;     // k offset 0..28, fixed per warp

#pragma unroll
    for (int kc = 0; kc < D / BK; ++kc) {
        const int gk4 = kc * (BK / 4) + (k4 >> 2);  // float4 column
#pragma unroll
        for (int it = 0; it < 4; ++it) {
            int r = lrow + it * 32;
            float4 ga = x4[(size_t)(rowBase + r) * (D / 4) + gk4];
            As[k4 + 0][r] = ga.x; As[k4 + 1][r] = ga.y;
            As[k4 + 2][r] = ga.z; As[k4 + 3][r] = ga.w;
            float4 gb = x4[(size_t)(colBase + r) * (D / 4) + gk4];
            Bs[k4 + 0][r] = gb.x; Bs[k4 + 1][r] = gb.y;
            Bs[k4 + 2][r] = gb.z; Bs[k4 + 3][r] = gb.w;
        }
        __syncthreads();
#pragma unroll
        for (int k = 0; k < BK; ++k) {
            float a[8], b[8];
            float4 t;
            t = *(const float4*)&As[k][ty * 4];
            a[0] = t.x; a[1] = t.y; a[2] = t.z; a[3] = t.w;
            t = *(const float4*)&As[k][64 + ty * 4];
            a[4] = t.x; a[5] = t.y; a[6] = t.z; a[7] = t.w;
            t = *(const float4*)&Bs[k][tx * 4];
            b[0] = t.x; b[1] = t.y; b[2] = t.z; b[3] = t.w;
            t = *(const float4*)&Bs[k][64 + tx * 4];
            b[4] = t.x; b[5] = t.y; b[6] = t.z; b[7] = t.w;
#pragma unroll
            for (int i = 0; i < 8; ++i)
#pragma unroll
                for (int j = 0; j < 8; ++j)
                    acc[i][j] = fmaf(a[i], b[j], acc[i][j]);
        }
        __syncthreads();
    }

    // Per-thread top-2 over its 8x8 micro-tile with upper-triangle mask.
    float v1 = -FLT_MAX, v2 = -FLT_MAX; int i1 = -1, i2 = -1;
#pragma unroll
    for (int ii = 0; ii < 8; ++ii) {
        int gi = rowBase + ((ii < 4) ? ty * 4 + ii : 64 + ty * 4 + (ii - 4));
#pragma unroll
        for (int jj = 0; jj < 8; ++jj) {
            int gj = colBase + ((jj < 4) ? tx * 4 + jj : 64 + tx * 4 + (jj - 4));
            if (gi < gj) ins2(v1, i1, v2, i2, acc[ii][jj], gi * N + gj);
        }
    }

    // Block tree-reduce of 256 top-2 records.
    __shared__ float sV[512];
    __shared__ int   sI[512];
    sV[2 * tid] = v1; sI[2 * tid] = i1;
    sV[2 * tid + 1] = v2; sI[2 * tid + 1] = i2;
    __syncthreads();
    for (int s = 128; s > 0; s >>= 1) {
        if (tid < s) {
            int o = 2 * (tid + s);
            ins2(v1, i1, v2, i2, sV[o], sI[o]);
            ins2(v1, i1, v2, i2, sV[o + 1], sI[o + 1]);
            sV[2 * tid] = v1; sI[2 * tid] = i1;
            sV[2 * tid + 1] = v2; sI[2 * tid + 1] = i2;
        }
        __syncthreads();
    }
    if (tid == 0) {
        g_blkV[bid * 2] = v1;     g_blkI[bid * 2] = i1;
        g_blkV[bid * 2 + 1] = v2; g_blkI[bid * 2 + 1] = i2;
    }
}

// Kernel 3: global top-2 over 8192 candidates, then mean of ratios (double acc).
__global__ void finalize_kernel(float* __restrict__ out) {
    __shared__ float sV[512];
    __shared__ int   sI[512];
    __shared__ double sD[256];
    const int t = threadIdx.x;

    float v1 = -FLT_MAX, v2 = -FLT_MAX; int i1 = -1, i2 = -1;
    for (int i = t; i < NT * NT * 2; i += 256)
        ins2(v1, i1, v2, i2, g_blkV[i], g_blkI[i]);

    sV[2 * t] = v1; sI[2 * t] = i1;
    sV[2 * t + 1] = v2; sI[2 * t + 1] = i2;
    __syncthreads();
    for (int s = 128; s > 0; s >>= 1) {
        if (t < s) {
            int o = 2 * (t + s);
            ins2(v1, i1, v2, i2, sV[o], sI[o]);
            ins2(v1, i1, v2, i2, sV[o + 1], sI[o + 1]);
            sV[2 * t] = v1; sI[2 * t] = i1;
            sV[2 * t + 1] = v2; sI[2 * t + 1] = i2;
        }
        __syncthreads();
    }
    // sV[0],sI[0] = global max; sV[1] = second.
    const float V1 = sV[0], V2 = sV[1];
    const int   I1 = sI[0];

    double sum = 0.0;
    for (int p = t; p < P; p += 256) {
        int sf = p * N + p + 1;                 // flat index of self pair (p, p+1)
        float v = (I1 == sf) ? V2 : V1;         // exclude person p's self pair
        sum += (double)v / (double)g_self[p];
    }
    sD[t] = sum;
    __syncthreads();
    for (int s = 128; s > 0; s >>= 1) {
        if (t < s) sD[t] += sD[t + s];
        __syncthreads();
    }
    if (t == 0) out[0] = (float)(sD[0] / (double)P);
}

extern "C" void kernel_launch(void* const* d_in, const int* in_sizes, int n_in,
                              void* d_out, int out_size) {
    const float* x = (const float*)d_in[0];
    float* out = (float*)d_out;

    self_kernel<<<P / 8, 256>>>(x);        // 8 warps/block, 512 blocks
    dim3 g(NT, NT);
    gram_kernel<<<g, 256>>>(x);
    finalize_kernel<<<1, 256>>>(out);
}

// round 3
// speedup vs baseline: 1.2141x; 1.2141x over previous
#include <cuda_runtime.h>
#include <float.h>

#define N 8192
#define D 128
#define P 4096
#define BM 128
#define BK 32
#define NT (N / BM)   // 64 tiles per dimension
#define SMP (BM + 4)  // padded row stride (132 floats)

// Persistent scratch (allocation-free rule): fully rewritten every launch.
__device__ float g_self[P];
__device__ float g_blkV[NT * NT * 2];
__device__ int   g_blkI[NT * NT * 2];

__device__ __forceinline__ void ins2(float& v1, int& i1, float& v2, int& i2,
                                     float v, int i) {
    if (v > v1) { v2 = v1; i2 = i1; v1 = v; i1 = i; }
    else if (v > v2) { v2 = v; i2 = i; }
}

// ---- packed f32x2 helpers (sm_103a FFMA2 path) ----
__device__ __forceinline__ unsigned long long pack_dup(float a) {
    unsigned long long r;
    asm("mov.b64 %0, {%1, %1};" : "=l"(r) : "f"(a));
    return r;
}
__device__ __forceinline__ void ffma2(unsigned long long& d,
                                      unsigned long long a,
                                      unsigned long long b) {
    asm("fma.rn.f32x2 %0, %1, %2, %3;" : "=l"(d) : "l"(a), "l"(b), "l"(d));
}
__device__ __forceinline__ void unpack2(unsigned long long v, float& lo, float& hi) {
    asm("mov.b64 {%0, %1}, %2;" : "=f"(lo), "=f"(hi) : "l"(v));
}

// Kernel 1: sim_self[p] = dot(x[p], x[p+1]), one warp per p.
__global__ void self_kernel(const float* __restrict__ x) {
    int w = (blockIdx.x * blockDim.x + threadIdx.x) >> 5;
    int lane = threadIdx.x & 31;
    if (w >= P) return;
    const float* a = x + (size_t)w * D;
    const float* b = x + (size_t)(w + 1) * D;
    float s = 0.f;
#pragma unroll
    for (int k = lane; k < D; k += 32) s = fmaf(a[k], b[k], s);
#pragma unroll
    for (int o = 16; o; o >>= 1) s += __shfl_xor_sync(0xffffffffu, s, o);
    if (lane == 0) g_self[w] = s;
}

// Kernel 2: 128x128 Gram tile via packed FFMA2, per-block top-2 of i<j entries.
__global__ __launch_bounds__(256, 2) void gram_kernel(const float* __restrict__ x) {
    const int bx = blockIdx.x, by = blockIdx.y;   // bx = col tile, by = row tile
    const int bid = by * NT + bx;
    if (bx < by) {
        if (threadIdx.x == 0) {
            g_blkV[bid * 2] = -FLT_MAX; g_blkV[bid * 2 + 1] = -FLT_MAX;
            g_blkI[bid * 2] = -1;       g_blkI[bid * 2 + 1] = -1;
        }
        return;
    }

    __shared__ __align__(16) float As[BK][SMP];  // K-transposed: As[k][row]
    __shared__ __align__(16) float Bs[BK][SMP];

    const int tid = threadIdx.x;
    const int tx = tid & 15, ty = tid >> 4;
    const int rowBase = by * BM, colBase = bx * BM;

    // accP[i][j2]: f32x2 pair = (acc[i][2*j2], acc[i][2*j2+1]) within the
    // thread's two 4-col groups (j2 0,1 -> cols tx*4+0..3; j2 2,3 -> 64+tx*4+0..3)
    unsigned long long accP[8][4];
#pragma unroll
    for (int i = 0; i < 8; ++i)
#pragma unroll
        for (int j = 0; j < 4; ++j) accP[i][j] = 0ull;

    const float4* __restrict__ x4 = (const float4*)x;
    const int lrow = tid & 31;          // row within 32-row group (distinct per warp)
    const int k4 = (tid >> 5) << 2;     // k offset 0..28, fixed per warp

#pragma unroll
    for (int kc = 0; kc < D / BK; ++kc) {
        const int gk4 = kc * (BK / 4) + (k4 >> 2);  // float4 column
#pragma unroll
        for (int it = 0; it < 4; ++it) {
            int r = lrow + it * 32;
            float4 ga = x4[(size_t)(rowBase + r) * (D / 4) + gk4];
            As[k4 + 0][r] = ga.x; As[k4 + 1][r] = ga.y;
            As[k4 + 2][r] = ga.z; As[k4 + 3][r] = ga.w;
            float4 gb = x4[(size_t)(colBase + r) * (D / 4) + gk4];
            Bs[k4 + 0][r] = gb.x; Bs[k4 + 1][r] = gb.y;
            Bs[k4 + 2][r] = gb.z; Bs[k4 + 3][r] = gb.w;
        }
        __syncthreads();
#pragma unroll
        for (int k = 0; k < BK; ++k) {
            // b pairs: natural f32x2 from contiguous smem (no extra instructions)
            ulonglong2 tb0 = *(const ulonglong2*)&Bs[k][tx * 4];
            ulonglong2 tb1 = *(const ulonglong2*)&Bs[k][64 + tx * 4];
            float4 ta0 = *(const float4*)&As[k][ty * 4];
            float4 ta1 = *(const float4*)&As[k][64 + ty * 4];
            float a[8] = {ta0.x, ta0.y, ta0.z, ta0.w, ta1.x, ta1.y, ta1.z, ta1.w};
            unsigned long long bP0 = tb0.x, bP1 = tb0.y, bP2 = tb1.x, bP3 = tb1.y;
#pragma unroll
            for (int i = 0; i < 8; ++i) {
                unsigned long long aP = pack_dup(a[i]);
                ffma2(accP[i][0], aP, bP0);
                ffma2(accP[i][1], aP, bP1);
                ffma2(accP[i][2], aP, bP2);
                ffma2(accP[i][3], aP, bP3);
            }
        }
        __syncthreads();
    }

    // Per-thread top-2 over its 8x8 micro-tile with upper-triangle mask.
    float v1 = -FLT_MAX, v2 = -FLT_MAX; int i1 = -1, i2 = -1;
#pragma unroll
    for (int ii = 0; ii < 8; ++ii) {
        int gi = rowBase + ((ii < 4) ? ty * 4 + ii : 64 + ty * 4 + (ii - 4));
#pragma unroll
        for (int j2 = 0; j2 < 4; ++j2) {
            int colOff = (j2 < 2) ? (tx * 4 + j2 * 2) : (64 + tx * 4 + (j2 - 2) * 2);
            float lo, hi;
            unpack2(accP[ii][j2], lo, hi);
            int gj0 = colBase + colOff;
            if (gi < gj0)     ins2(v1, i1, v2, i2, lo, gi * N + gj0);
            if (gi < gj0 + 1) ins2(v1, i1, v2, i2, hi, gi * N + gj0 + 1);
        }
    }

    // Block tree-reduce of 256 top-2 records.
    __shared__ float sV[512];
    __shared__ int   sI[512];
    sV[2 * tid] = v1; sI[2 * tid] = i1;
    sV[2 * tid + 1] = v2; sI[2 * tid + 1] = i2;
    __syncthreads();
    for (int s = 128; s > 0; s >>= 1) {
        if (tid < s) {
            int o = 2 * (tid + s);
            ins2(v1, i1, v2, i2, sV[o], sI[o]);
            ins2(v1, i1, v2, i2, sV[o + 1], sI[o + 1]);
            sV[2 * tid] = v1; sI[2 * tid] = i1;
            sV[2 * tid + 1] = v2; sI[2 * tid + 1] = i2;
        }
        __syncthreads();
    }
    if (tid == 0) {
        g_blkV[bid * 2] = v1;     g_blkI[bid * 2] = i1;
        g_blkV[bid * 2 + 1] = v2; g_blkI[bid * 2 + 1] = i2;
    }
}

// Kernel 3: global top-2 over 8192 candidates, then mean of ratios (double acc).
__global__ void finalize_kernel(float* __restrict__ out) {
    __shared__ float sV[512];
    __shared__ int   sI[512];
    __shared__ double sD[256];
    const int t = threadIdx.x;

    float v1 = -FLT_MAX, v2 = -FLT_MAX; int i1 = -1, i2 = -1;
    for (int i = t; i < NT * NT * 2; i += 256)
        ins2(v1, i1, v2, i2, g_blkV[i], g_blkI[i]);

    sV[2 * t] = v1; sI[2 * t] = i1;
    sV[2 * t + 1] = v2; sI[2 * t + 1] = i2;
    __syncthreads();
    for (int s = 128; s > 0; s >>= 1) {
        if (t < s) {
            int o = 2 * (t + s);
            ins2(v1, i1, v2, i2, sV[o], sI[o]);
            ins2(v1, i1, v2, i2, sV[o + 1], sI[o + 1]);
            sV[2 * t] = v1; sI[2 * t] = i1;
            sV[2 * t + 1] = v2; sI[2 * t + 1] = i2;
        }
        __syncthreads();
    }
    // sV[0],sI[0] = global max; sV[1] = second.
    const float V1 = sV[0], V2 = sV[1];
    const int   I1 = sI[0];

    double sum = 0.0;
    for (int p = t; p < P; p += 256) {
        int sf = p * N + p + 1;                 // flat index of self pair (p, p+1)
        float v = (I1 == sf) ? V2 : V1;         // exclude person p's self pair
        sum += (double)v / (double)g_self[p];
    }
    sD[t] = sum;
    __syncthreads();
    for (int s = 128; s > 0; s >>= 1) {
        if (t < s) sD[t] += sD[t + s];
        __syncthreads();
    }
    if (t == 0) out[0] = (float)(sD[0] / (double)P);
}

extern "C" void kernel_launch(void* const* d_in, const int* in_sizes, int n_in,
                              void* d_out, int out_size) {
    const float* x = (const float*)d_in[0];
    float* out = (float*)d_out;

    self_kernel<<<P / 8, 256>>>(x);        // 8 warps/block, 512 blocks
    dim3 g(NT, NT);
    gram_kernel<<<g, 256>>>(x);
    finalize_kernel<<<1, 256>>>(out);
}

// round 5
// speedup vs baseline: 1.2229x; 1.0073x over previous
#include <cuda_runtime.h>
#include <cuda_bf16.h>
#include <float.h>
#include <stdint.h>

#define N 8192
#define D 128
#define P 4096
#define BM 128
#define NT (N / BM)   // 64 tiles per dimension

// ---- persistent scratch (allocation-free rule): fully rewritten every launch ----
__device__ float g_self[P];
__device__ float g_blkV[NT * NT * 2];
__device__ int   g_blkI[NT * NT * 2];
__device__ __nv_bfloat16 g_xhi[N * D];
__device__ __nv_bfloat16 g_xlo[N * D];

// dynamic smem: 4 tiles of 128 rows x 256B (bf16 x 128), granule-swizzled
#define TILE_BYTES 32768
#define OFF_AHI 0
#define OFF_ALO (1 * TILE_BYTES)
#define OFF_BHI (2 * TILE_BYTES)
#define OFF_BLO (3 * TILE_BYTES)
#define DSMEM_TOTAL (4 * TILE_BYTES + 1024)

__device__ __forceinline__ void ins2(float& v1, int& i1, float& v2, int& i2,
                                     float v, int i) {
    if (v > v1) { v2 = v1; i2 = i1; v1 = v; i1 = i; }
    else if (v > v2) { v2 = v; i2 = i; }
}

__device__ __forceinline__ uint32_t smem_u32(const void* p) {
    uint32_t a;
    asm("{ .reg .u64 t; cvta.to.shared.u64 t, %1; cvt.u32.u64 %0, t; }"
        : "=r"(a) : "l"(p));
    return a;
}
__device__ __forceinline__ void ldmx4(uint32_t r[4], uint32_t addr) {
    asm volatile("ldmatrix.sync.aligned.m8n8.x4.shared.b16 {%0,%1,%2,%3}, [%4];"
                 : "=r"(r[0]), "=r"(r[1]), "=r"(r[2]), "=r"(r[3]) : "r"(addr));
}
__device__ __forceinline__ void mma16816(float d[4], const uint32_t a[4],
                                         uint32_t b0, uint32_t b1) {
    asm volatile(
        "mma.sync.aligned.m16n8k16.row.col.f32.bf16.bf16.f32 "
        "{%0,%1,%2,%3}, {%4,%5,%6,%7}, {%8,%9}, {%0,%1,%2,%3};"
        : "+f"(d[0]), "+f"(d[1]), "+f"(d[2]), "+f"(d[3])
        : "r"(a[0]), "r"(a[1]), "r"(a[2]), "r"(a[3]), "r"(b0), "r"(b1));
}

// Kernel 0: fp32 -> bf16 hi/lo split.
__global__ void convert_kernel(const float* __restrict__ x) {
    int i = blockIdx.x * 256 + threadIdx.x;
    float v = x[i];
    __nv_bfloat16 h = __float2bfloat16(v);
    g_xhi[i] = h;
    g_xlo[i] = __float2bfloat16(v - __bfloat162float(h));
}

// Kernel 1: sim_self[p] = dot(x[p], x[p+1]) in exact fp32 (one warp per p).
__global__ void self_kernel(const float* __restrict__ x) {
    int w = (blockIdx.x * blockDim.x + threadIdx.x) >> 5;
    int lane = threadIdx.x & 31;
    if (w >= P) return;
    const float* a = x + (size_t)w * D;
    const float* b = x + (size_t)(w + 1) * D;
    float s = 0.f;
#pragma unroll
    for (int k = lane; k < D; k += 32) s = fmaf(a[k], b[k], s);
#pragma unroll
    for (int o = 16; o; o >>= 1) s += __shfl_xor_sync(0xffffffffu, s, o);
    if (lane == 0) g_self[w] = s;
}

// Kernel 2: HMMA (mma.sync bf16-split) 128x128 Gram tile, per-block top-2 of i<j.
__global__ __launch_bounds__(256, 1) void gram_hmma_kernel() {
    const int bx = blockIdx.x, by = blockIdx.y;
    const int bid = by * NT + bx;
    const int tid = threadIdx.x;
    if (bx < by) {
        if (tid == 0) {
            g_blkV[bid * 2] = -FLT_MAX; g_blkV[bid * 2 + 1] = -FLT_MAX;
            g_blkI[bid * 2] = -1;       g_blkI[bid * 2 + 1] = -1;
        }
        return;
    }

    extern __shared__ char dsm_raw[];
    char* dsm = (char*)(((uintptr_t)dsm_raw + 1023) & ~(uintptr_t)1023);
    const uint32_t sbase = smem_u32(dsm);
    const int wid = tid >> 5, lane = tid & 31;
    const int wm = wid & 1, wn = wid >> 1;          // warp tile: rows wm*64, cols wn*32
    const int rowBase = by * BM, colBase = bx * BM;

    // ---- load 4 tiles (A hi/lo, B hi/lo) with granule swizzle ----
    {
        const uint4* __restrict__ xhi4 = (const uint4*)g_xhi;
        const uint4* __restrict__ xlo4 = (const uint4*)g_xlo;
#pragma unroll
        for (int t = tid; t < 2048; t += 256) {
            int row = t >> 4, g = t & 15;
            uint32_t dst = (uint32_t)row * 256 + (uint32_t)((g ^ (row & 7)) << 4);
            size_t ia = (size_t)(rowBase + row) * 16 + g;
            size_t ib = (size_t)(colBase + row) * 16 + g;
            *(uint4*)(dsm + OFF_AHI + dst) = xhi4[ia];
            *(uint4*)(dsm + OFF_ALO + dst) = xlo4[ia];
            *(uint4*)(dsm + OFF_BHI + dst) = xhi4[ib];
            *(uint4*)(dsm + OFF_BLO + dst) = xlo4[ib];
        }
    }
    __syncthreads();

    // ---- per-lane ldmatrix addressing (row-dependent parts precomputed) ----
    const int lrow8 = lane & 7;
    const int lm01 = (lane >> 3) & 1;   // +8 rows for matrices 1,3
    const int lh   = lane >> 4;         // k-half for matrices 2,3
    uint32_t aoff[4], boff[2];
    int a7[4], b7[2];
#pragma unroll
    for (int mt = 0; mt < 4; ++mt) {
        int r = wm * 64 + mt * 16 + lrow8 + lm01 * 8;
        aoff[mt] = (uint32_t)r * 256; a7[mt] = r & 7;
    }
#pragma unroll
    for (int q = 0; q < 2; ++q) {
        int r = wn * 32 + q * 16 + lrow8 + lm01 * 8;
        boff[q] = (uint32_t)r * 256; b7[q] = r & 7;
    }

    float acc[4][4][4];
#pragma unroll
    for (int mt = 0; mt < 4; ++mt)
#pragma unroll
        for (int nt = 0; nt < 4; ++nt)
#pragma unroll
            for (int r = 0; r < 4; ++r) acc[mt][nt][r] = 0.f;

    const uint32_t passA[3] = {OFF_AHI, OFF_AHI, OFF_ALO};
    const uint32_t passB[3] = {OFF_BHI, OFF_BLO, OFF_BHI};

#pragma unroll
    for (int pass = 0; pass < 3; ++pass) {
        const uint32_t Ab = sbase + passA[pass];
        const uint32_t Bb = sbase + passB[pass];
#pragma unroll
        for (int ks = 0; ks < 8; ++ks) {
            uint32_t afr[4][4], bfr[4][2];
#pragma unroll
            for (int mt = 0; mt < 4; ++mt)
                ldmx4(afr[mt], Ab + aoff[mt]
                               + (uint32_t)(((2 * ks + lh) ^ a7[mt]) << 4));
#pragma unroll
            for (int q = 0; q < 2; ++q) {
                uint32_t tmp[4];
                ldmx4(tmp, Bb + boff[q]
                           + (uint32_t)(((2 * ks + lh) ^ b7[q]) << 4));
                bfr[2 * q][0] = tmp[0]; bfr[2 * q][1] = tmp[2];
                bfr[2 * q + 1][0] = tmp[1]; bfr[2 * q + 1][1] = tmp[3];
            }
#pragma unroll
            for (int mt = 0; mt < 4; ++mt)
#pragma unroll
                for (int nt = 0; nt < 4; ++nt)
                    mma16816(acc[mt][nt], afr[mt], bfr[nt][0], bfr[nt][1]);
        }
    }

    // ---- epilogue: top-2 with i<j mask (d-frag mapping of m16n8) ----
    float v1 = -FLT_MAX, v2 = -FLT_MAX; int i1 = -1, i2 = -1;
    const int grow = rowBase + wm * 64 + (lane >> 2);
    const int gcol = colBase + wn * 32 + (lane & 3) * 2;
#pragma unroll
    for (int mt = 0; mt < 4; ++mt)
#pragma unroll
        for (int nt = 0; nt < 4; ++nt) {
            int gi = grow + mt * 16;
            int gj = gcol + nt * 8;
            if (gi < gj)         ins2(v1, i1, v2, i2, acc[mt][nt][0], gi * N + gj);
            if (gi < gj + 1)     ins2(v1, i1, v2, i2, acc[mt][nt][1], gi * N + gj + 1);
            if (gi + 8 < gj)     ins2(v1, i1, v2, i2, acc[mt][nt][2], (gi + 8) * N + gj);
            if (gi + 8 < gj + 1) ins2(v1, i1, v2, i2, acc[mt][nt][3], (gi + 8) * N + gj + 1);
        }

    // ---- block tree-reduce of 256 top-2 records ----
    __shared__ float sV[512];
    __shared__ int   sI[512];
    sV[2 * tid] = v1; sI[2 * tid] = i1;
    sV[2 * tid + 1] = v2; sI[2 * tid + 1] = i2;
    __syncthreads();
    for (int s = 128; s > 0; s >>= 1) {
        if (tid < s) {
            int o = 2 * (tid + s);
            ins2(v1, i1, v2, i2, sV[o], sI[o]);
            ins2(v1, i1, v2, i2, sV[o + 1], sI[o + 1]);
            sV[2 * tid] = v1; sI[2 * tid] = i1;
            sV[2 * tid + 1] = v2; sI[2 * tid + 1] = i2;
        }
        __syncthreads();
    }
    if (tid == 0) {
        g_blkV[bid * 2] = v1;     g_blkI[bid * 2] = i1;
        g_blkV[bid * 2 + 1] = v2; g_blkI[bid * 2 + 1] = i2;
    }
}

// Kernel 3: global top-2 over 8192 candidates, then mean of ratios (double acc).
__global__ void finalize_kernel(float* __restrict__ out) {
    __shared__ float sV[512];
    __shared__ int   sI[512];
    __shared__ double sD[256];
    const int t = threadIdx.x;

    float v1 = -FLT_MAX, v2 = -FLT_MAX; int i1 = -1, i2 = -1;
    for (int i = t; i < NT * NT * 2; i += 256)
        ins2(v1, i1, v2, i2, g_blkV[i], g_blkI[i]);

    sV[2 * t] = v1; sI[2 * t] = i1;
    sV[2 * t + 1] = v2; sI[2 * t + 1] = i2;
    __syncthreads();
    for (int s = 128; s > 0; s >>= 1) {
        if (t < s) {
            int o = 2 * (t + s);
            ins2(v1, i1, v2, i2, sV[o], sI[o]);
            ins2(v1, i1, v2, i2, sV[o + 1], sI[o + 1]);
            sV[2 * t] = v1; sI[2 * t] = i1;
            sV[2 * t + 1] = v2; sI[2 * t + 1] = i2;
        }
        __syncthreads();
    }
    const float V1 = sV[0], V2 = sV[1];
    const int   I1 = sI[0];

    double sum = 0.0;
    for (int p = t; p < P; p += 256) {
        int sf = p * N + p + 1;
        float v = (I1 == sf) ? V2 : V1;
        sum += (double)v / (double)g_self[p];
    }
    sD[t] = sum;
    __syncthreads();
    for (int s = 128; s > 0; s >>= 1) {
        if (t < s) sD[t] += sD[t + s];
        __syncthreads();
    }
    if (t == 0) out[0] = (float)(sD[0] / (double)P);
}

extern "C" void kernel_launch(void* const* d_in, const int* in_sizes, int n_in,
                              void* d_out, int out_size) {
    const float* x = (const float*)d_in[0];
    float* out = (float*)d_out;

    cudaFuncSetAttribute(gram_hmma_kernel,
                         cudaFuncAttributeMaxDynamicSharedMemorySize, DSMEM_TOTAL);

    convert_kernel<<<(N * D) / 256, 256>>>(x);
    self_kernel<<<P / 8, 256>>>(x);
    dim3 g(NT, NT);
    gram_hmma_kernel<<<g, 256, DSMEM_TOTAL>>>();
    finalize_kernel<<<1, 256>>>(out);
}

// round 6
// speedup vs baseline: 1.3175x; 1.0773x over previous
#include <cuda_runtime.h>
#include <cuda_bf16.h>
#include <float.h>
#include <stdint.h>

#define N 8192
#define D 128
#define P 4096
#define BM 128
#define NT (N / BM)   // 64 tiles per dimension

// ---- persistent scratch (allocation-free rule): fully rewritten every launch ----
__device__ float g_self[P];
__device__ float g_blkV[NT * NT * 2];
__device__ int   g_blkI[NT * NT * 2];
__device__ __nv_bfloat16 g_xhi[N * D];
__device__ __nv_bfloat16 g_xlo[N * D];
__device__ float  g_topV[2];
__device__ int    g_topI[1];
__device__ double g_part[16];

// dynamic smem: 4 tiles of 128 rows x 256B (bf16 x 128), granule-swizzled
#define TILE_BYTES 32768
#define OFF_AHI 0
#define OFF_ALO (1 * TILE_BYTES)
#define OFF_BHI (2 * TILE_BYTES)
#define OFF_BLO (3 * TILE_BYTES)
#define DSMEM_TOTAL (4 * TILE_BYTES + 1024)

__device__ __forceinline__ void ins2(float& v1, int& i1, float& v2, int& i2,
                                     float v, int i) {
    if (v > v1) { v2 = v1; i2 = i1; v1 = v; i1 = i; }
    else if (v > v2) { v2 = v; i2 = i; }
}

__device__ __forceinline__ uint32_t smem_u32(const void* p) {
    uint32_t a;
    asm("{ .reg .u64 t; cvta.to.shared.u64 t, %1; cvt.u32.u64 %0, t; }"
        : "=r"(a) : "l"(p));
    return a;
}
__device__ __forceinline__ void ldmx4(uint32_t r[4], uint32_t addr) {
    asm volatile("ldmatrix.sync.aligned.m8n8.x4.shared.b16 {%0,%1,%2,%3}, [%4];"
                 : "=r"(r[0]), "=r"(r[1]), "=r"(r[2]), "=r"(r[3]) : "r"(addr));
}
__device__ __forceinline__ void mma16816(float d[4], const uint32_t a[4],
                                         uint32_t b0, uint32_t b1) {
    asm volatile(
        "mma.sync.aligned.m16n8k16.row.col.f32.bf16.bf16.f32 "
        "{%0,%1,%2,%3}, {%4,%5,%6,%7}, {%8,%9}, {%0,%1,%2,%3};"
        : "+f"(d[0]), "+f"(d[1]), "+f"(d[2]), "+f"(d[3])
        : "r"(a[0]), "r"(a[1]), "r"(a[2]), "r"(a[3]), "r"(b0), "r"(b1));
}

// Kernel 0: fp32 -> bf16 hi/lo split.
__global__ void convert_kernel(const float* __restrict__ x) {
    int i = blockIdx.x * 256 + threadIdx.x;
    float v = x[i];
    __nv_bfloat16 h = __float2bfloat16(v);
    g_xhi[i] = h;
    g_xlo[i] = __float2bfloat16(v - __bfloat162float(h));
}

// Kernel 1: sim_self[p] = dot(x[p], x[p+1]) in exact fp32 (one warp per p).
__global__ void self_kernel(const float* __restrict__ x) {
    int w = (blockIdx.x * blockDim.x + threadIdx.x) >> 5;
    int lane = threadIdx.x & 31;
    if (w >= P) return;
    const float* a = x + (size_t)w * D;
    const float* b = x + (size_t)(w + 1) * D;
    float s = 0.f;
#pragma unroll
    for (int k = lane; k < D; k += 32) s = fmaf(a[k], b[k], s);
#pragma unroll
    for (int o = 16; o; o >>= 1) s += __shfl_xor_sync(0xffffffffu, s, o);
    if (lane == 0) g_self[w] = s;
}

// Kernel 2: HMMA bf16-split 128x128 Gram tile (pipelined), per-block top-2 of i<j.
__global__ __launch_bounds__(256, 1) void gram_hmma_kernel() {
    const int bx = blockIdx.x, by = blockIdx.y;
    const int bid = by * NT + bx;
    const int tid = threadIdx.x;
    if (bx < by) {
        if (tid == 0) {
            g_blkV[bid * 2] = -FLT_MAX; g_blkV[bid * 2 + 1] = -FLT_MAX;
            g_blkI[bid * 2] = -1;       g_blkI[bid * 2 + 1] = -1;
        }
        return;
    }

    extern __shared__ char dsm_raw[];
    char* dsm = (char*)(((uintptr_t)dsm_raw + 1023) & ~(uintptr_t)1023);
    const uint32_t sbase = smem_u32(dsm);
    const int wid = tid >> 5, lane = tid & 31;
    const int wm = wid & 1, wn = wid >> 1;          // warp tile: rows wm*64, cols wn*32
    const int rowBase = by * BM, colBase = bx * BM;

    // ---- load 4 tiles (A hi/lo, B hi/lo) with granule swizzle ----
    {
        const uint4* __restrict__ xhi4 = (const uint4*)g_xhi;
        const uint4* __restrict__ xlo4 = (const uint4*)g_xlo;
#pragma unroll
        for (int t = tid; t < 2048; t += 256) {
            int row = t >> 4, g = t & 15;
            uint32_t dst = (uint32_t)row * 256 + (uint32_t)((g ^ (row & 7)) << 4);
            size_t ia = (size_t)(rowBase + row) * 16 + g;
            size_t ib = (size_t)(colBase + row) * 16 + g;
            *(uint4*)(dsm + OFF_AHI + dst) = xhi4[ia];
            *(uint4*)(dsm + OFF_ALO + dst) = xlo4[ia];
            *(uint4*)(dsm + OFF_BHI + dst) = xhi4[ib];
            *(uint4*)(dsm + OFF_BLO + dst) = xlo4[ib];
        }
    }
    __syncthreads();

    // ---- per-lane ldmatrix addressing ----
    const int lrow8 = lane & 7;
    const int lm01 = (lane >> 3) & 1;
    const int lh   = lane >> 4;
    uint32_t aoff[4], boff[2];
    int a7[4], b7[2];
#pragma unroll
    for (int mt = 0; mt < 4; ++mt) {
        int r = wm * 64 + mt * 16 + lrow8 + lm01 * 8;
        aoff[mt] = (uint32_t)r * 256; a7[mt] = r & 7;
    }
#pragma unroll
    for (int q = 0; q < 2; ++q) {
        int r = wn * 32 + q * 16 + lrow8 + lm01 * 8;
        boff[q] = (uint32_t)r * 256; b7[q] = r & 7;
    }

    float acc[4][4][4];
#pragma unroll
    for (int mt = 0; mt < 4; ++mt)
#pragma unroll
        for (int nt = 0; nt < 4; ++nt)
#pragma unroll
            for (int r = 0; r < 4; ++r) acc[mt][nt][r] = 0.f;

    const uint32_t passA[3] = {OFF_AHI, OFF_AHI, OFF_ALO};
    const uint32_t passB[3] = {OFF_BHI, OFF_BLO, OFF_BHI};

    // Fragment loader for flattened iteration it = pass*8 + ks.
    auto load_frags = [&](int it, uint32_t afr[4][4], uint32_t bfr[4][2]) {
        const int pass = it >> 3, ks = it & 7;
        const uint32_t Ab = sbase + passA[pass];
        const uint32_t Bb = sbase + passB[pass];
#pragma unroll
        for (int mt = 0; mt < 4; ++mt)
            ldmx4(afr[mt], Ab + aoff[mt]
                           + (uint32_t)(((2 * ks + lh) ^ a7[mt]) << 4));
#pragma unroll
        for (int q = 0; q < 2; ++q) {
            uint32_t tmp[4];
            ldmx4(tmp, Bb + boff[q]
                       + (uint32_t)(((2 * ks + lh) ^ b7[q]) << 4));
            bfr[2 * q][0] = tmp[0]; bfr[2 * q][1] = tmp[2];
            bfr[2 * q + 1][0] = tmp[1]; bfr[2 * q + 1][1] = tmp[3];
        }
    };

    // ---- software-pipelined mainloop: prefetch it+1 before MMAs of it ----
    uint32_t afr[2][4][4], bfr[2][4][2];
    load_frags(0, afr[0], bfr[0]);
#pragma unroll
    for (int it = 0; it < 24; ++it) {
        const int cur = it & 1, nxt = cur ^ 1;
        if (it < 23) load_frags(it + 1, afr[nxt], bfr[nxt]);
#pragma unroll
        for (int mt = 0; mt < 4; ++mt)
#pragma unroll
            for (int nt = 0; nt < 4; ++nt)
                mma16816(acc[mt][nt], afr[cur][mt],
                         bfr[cur][nt][0], bfr[cur][nt][1]);
    }

    // ---- epilogue: top-2 (strict-upper blocks skip the i<j predicates) ----
    float v1 = -FLT_MAX, v2 = -FLT_MAX; int i1 = -1, i2 = -1;
    const int grow = rowBase + wm * 64 + (lane >> 2);
    const int gcol = colBase + wn * 32 + (lane & 3) * 2;
    if (bx > by) {
#pragma unroll
        for (int mt = 0; mt < 4; ++mt)
#pragma unroll
            for (int nt = 0; nt < 4; ++nt) {
                int gi = grow + mt * 16, gj = gcol + nt * 8;
                ins2(v1, i1, v2, i2, acc[mt][nt][0], gi * N + gj);
                ins2(v1, i1, v2, i2, acc[mt][nt][1], gi * N + gj + 1);
                ins2(v1, i1, v2, i2, acc[mt][nt][2], (gi + 8) * N + gj);
                ins2(v1, i1, v2, i2, acc[mt][nt][3], (gi + 8) * N + gj + 1);
            }
    } else {
#pragma unroll
        for (int mt = 0; mt < 4; ++mt)
#pragma unroll
            for (int nt = 0; nt < 4; ++nt) {
                int gi = grow + mt * 16, gj = gcol + nt * 8;
                if (gi < gj)         ins2(v1, i1, v2, i2, acc[mt][nt][0], gi * N + gj);
                if (gi < gj + 1)     ins2(v1, i1, v2, i2, acc[mt][nt][1], gi * N + gj + 1);
                if (gi + 8 < gj)     ins2(v1, i1, v2, i2, acc[mt][nt][2], (gi + 8) * N + gj);
                if (gi + 8 < gj + 1) ins2(v1, i1, v2, i2, acc[mt][nt][3], (gi + 8) * N + gj + 1);
            }
    }

    // ---- block tree-reduce of 256 top-2 records ----
    __shared__ float sV[512];
    __shared__ int   sI[512];
    sV[2 * tid] = v1; sI[2 * tid] = i1;
    sV[2 * tid + 1] = v2; sI[2 * tid + 1] = i2;
    __syncthreads();
    for (int s = 128; s > 0; s >>= 1) {
        if (tid < s) {
            int o = 2 * (tid + s);
            ins2(v1, i1, v2, i2, sV[o], sI[o]);
            ins2(v1, i1, v2, i2, sV[o + 1], sI[o + 1]);
            sV[2 * tid] = v1; sI[2 * tid] = i1;
            sV[2 * tid + 1] = v2; sI[2 * tid + 1] = i2;
        }
        __syncthreads();
    }
    if (tid == 0) {
        g_blkV[bid * 2] = v1;     g_blkI[bid * 2] = i1;
        g_blkV[bid * 2 + 1] = v2; g_blkI[bid * 2 + 1] = i2;
    }
}

// Kernel 3a: global top-2 over 8192 candidates (1 block).
__global__ void top2_kernel() {
    __shared__ float sV[512];
    __shared__ int   sI[512];
    const int t = threadIdx.x;

    float v1 = -FLT_MAX, v2 = -FLT_MAX; int i1 = -1, i2 = -1;
    for (int i = t; i < NT * NT * 2; i += 256)
        ins2(v1, i1, v2, i2, g_blkV[i], g_blkI[i]);

    sV[2 * t] = v1; sI[2 * t] = i1;
    sV[2 * t + 1] = v2; sI[2 * t + 1] = i2;
    __syncthreads();
    for (int s = 128; s > 0; s >>= 1) {
        if (t < s) {
            int o = 2 * (t + s);
            ins2(v1, i1, v2, i2, sV[o], sI[o]);
            ins2(v1, i1, v2, i2, sV[o + 1], sI[o + 1]);
            sV[2 * t] = v1; sI[2 * t] = i1;
            sV[2 * t + 1] = v2; sI[2 * t + 1] = i2;
        }
        __syncthreads();
    }
    if (t == 0) {
        g_topV[0] = sV[0]; g_topV[1] = sV[1]; g_topI[0] = sI[0];
    }
}

// Kernel 3b: per-block partial ratio sums (16 blocks x 256 threads, 1 p each).
__global__ void ratio_kernel() {
    __shared__ double sD[256];
    const int t = threadIdx.x;
    const int p = blockIdx.x * 256 + t;
    const float V1 = g_topV[0], V2 = g_topV[1];
    const int   I1 = g_topI[0];

    int sf = p * N + p + 1;
    float v = (I1 == sf) ? V2 : V1;
    sD[t] = (double)v / (double)g_self[p];
    __syncthreads();
    for (int s = 128; s > 0; s >>= 1) {
        if (t < s) sD[t] += sD[t + s];
        __syncthreads();
    }
    if (t == 0) g_part[blockIdx.x] = sD[0];
}

// Kernel 3c: deterministic combine.
__global__ void combine_kernel(float* __restrict__ out) {
    double s = 0.0;
#pragma unroll
    for (int i = 0; i < 16; ++i) s += g_part[i];
    out[0] = (float)(s / (double)P);
}

extern "C" void kernel_launch(void* const* d_in, const int* in_sizes, int n_in,
                              void* d_out, int out_size) {
    const float* x = (const float*)d_in[0];
    float* out = (float*)d_out;

    cudaFuncSetAttribute(gram_hmma_kernel,
                         cudaFuncAttributeMaxDynamicSharedMemorySize, DSMEM_TOTAL);

    convert_kernel<<<(N * D) / 256, 256>>>(x);
    self_kernel<<<P / 8, 256>>>(x);
    dim3 g(NT, NT);
    gram_hmma_kernel<<<g, 256, DSMEM_TOTAL>>>();
    top2_kernel<<<1, 256>>>();
    ratio_kernel<<<16, 256>>>();
    combine_kernel<<<1, 1>>>(out);
}

// round 7
// speedup vs baseline: 3.0742x; 2.3333x over previous
#include <cuda_runtime.h>
#include <cuda_bf16.h>
#include <float.h>
#include <stdint.h>

#define N 8192
#define D 128
#define P 4096
#define BM 128
#define NT (N / BM)   // 64 tiles per dimension
#define NCAND 8

// ---- persistent scratch (allocation-free rule): fully rewritten every launch ----
__device__ float g_self[P];
__device__ float g_blkV[NT * NT * 2];
__device__ int   g_blkI[NT * NT * 2];
__device__ __nv_bfloat16 g_xhi[N * D];
__device__ float  g_topV[2];
__device__ int    g_topI[1];
__device__ double g_part[16];

// dynamic smem: 2 tiles of 128 rows x 256B (bf16 x 128), granule-swizzled
#define TILE_BYTES 32768
#define OFF_AHI 0
#define OFF_BHI TILE_BYTES
#define DSMEM_TOTAL (2 * TILE_BYTES + 1024)
#define CAND_SMEM (NT * NT * 2 * 8)   // 8192 x (float+int) = 64KB

__device__ __forceinline__ void ins2(float& v1, int& i1, float& v2, int& i2,
                                     float v, int i) {
    if (v > v1) { v2 = v1; i2 = i1; v1 = v; i1 = i; }
    else if (v > v2) { v2 = v; i2 = i; }
}

__device__ __forceinline__ uint32_t smem_u32(const void* p) {
    uint32_t a;
    asm("{ .reg .u64 t; cvta.to.shared.u64 t, %1; cvt.u32.u64 %0, t; }"
        : "=r"(a) : "l"(p));
    return a;
}
__device__ __forceinline__ void ldmx4(uint32_t r[4], uint32_t addr) {
    asm volatile("ldmatrix.sync.aligned.m8n8.x4.shared.b16 {%0,%1,%2,%3}, [%4];"
                 : "=r"(r[0]), "=r"(r[1]), "=r"(r[2]), "=r"(r[3]) : "r"(addr));
}
__device__ __forceinline__ void mma16816(float d[4], const uint32_t a[4],
                                         uint32_t b0, uint32_t b1) {
    asm volatile(
        "mma.sync.aligned.m16n8k16.row.col.f32.bf16.bf16.f32 "
        "{%0,%1,%2,%3}, {%4,%5,%6,%7}, {%8,%9}, {%0,%1,%2,%3};"
        : "+f"(d[0]), "+f"(d[1]), "+f"(d[2]), "+f"(d[3])
        : "r"(a[0]), "r"(a[1]), "r"(a[2]), "r"(a[3]), "r"(b0), "r"(b1));
}

// Kernel 0: fp32 -> bf16 hi (screening precision).
__global__ void convert_kernel(const float* __restrict__ x) {
    int i = blockIdx.x * 256 + threadIdx.x;
    g_xhi[i] = __float2bfloat16(x[i]);
}

// Kernel 1: sim_self[p] = dot(x[p], x[p+1]) in exact fp32 (one warp per p).
__global__ void self_kernel(const float* __restrict__ x) {
    int w = (blockIdx.x * blockDim.x + threadIdx.x) >> 5;
    int lane = threadIdx.x & 31;
    if (w >= P) return;
    const float* a = x + (size_t)w * D;
    const float* b = x + (size_t)(w + 1) * D;
    float s = 0.f;
#pragma unroll
    for (int k = lane; k < D; k += 32) s = fmaf(a[k], b[k], s);
#pragma unroll
    for (int o = 16; o; o >>= 1) s += __shfl_xor_sync(0xffffffffu, s, o);
    if (lane == 0) g_self[w] = s;
}

// Kernel 2: single-pass hi*hi HMMA 128x128 Gram tile; per-block top-2 of i<j.
__global__ __launch_bounds__(256, 2) void gram_hmma_kernel() {
    const int bx = blockIdx.x, by = blockIdx.y;
    const int bid = by * NT + bx;
    const int tid = threadIdx.x;
    if (bx < by) {
        if (tid == 0) {
            g_blkV[bid * 2] = -FLT_MAX; g_blkV[bid * 2 + 1] = -FLT_MAX;
            g_blkI[bid * 2] = -1;       g_blkI[bid * 2 + 1] = -1;
        }
        return;
    }

    extern __shared__ char dsm_raw[];
    char* dsm = (char*)(((uintptr_t)dsm_raw + 1023) & ~(uintptr_t)1023);
    const uint32_t sbase = smem_u32(dsm);
    const int wid = tid >> 5, lane = tid & 31;
    const int wm = wid & 1, wn = wid >> 1;          // warp tile: rows wm*64, cols wn*32
    const int rowBase = by * BM, colBase = bx * BM;

    // ---- load A-hi / B-hi tiles with granule swizzle ----
    {
        const uint4* __restrict__ xhi4 = (const uint4*)g_xhi;
#pragma unroll
        for (int t = tid; t < 2048; t += 256) {
            int row = t >> 4, g = t & 15;
            uint32_t dst = (uint32_t)row * 256 + (uint32_t)((g ^ (row & 7)) << 4);
            *(uint4*)(dsm + OFF_AHI + dst) = xhi4[(size_t)(rowBase + row) * 16 + g];
            *(uint4*)(dsm + OFF_BHI + dst) = xhi4[(size_t)(colBase + row) * 16 + g];
        }
    }
    __syncthreads();

    // ---- per-lane ldmatrix addressing ----
    const int lrow8 = lane & 7;
    const int lm01 = (lane >> 3) & 1;
    const int lh   = lane >> 4;
    uint32_t aoff[4], boff[2];
    int a7[4], b7[2];
#pragma unroll
    for (int mt = 0; mt < 4; ++mt) {
        int r = wm * 64 + mt * 16 + lrow8 + lm01 * 8;
        aoff[mt] = (uint32_t)r * 256; a7[mt] = r & 7;
    }
#pragma unroll
    for (int q = 0; q < 2; ++q) {
        int r = wn * 32 + q * 16 + lrow8 + lm01 * 8;
        boff[q] = (uint32_t)r * 256; b7[q] = r & 7;
    }

    float acc[4][4][4];
#pragma unroll
    for (int mt = 0; mt < 4; ++mt)
#pragma unroll
        for (int nt = 0; nt < 4; ++nt)
#pragma unroll
            for (int r = 0; r < 4; ++r) acc[mt][nt][r] = 0.f;

    const uint32_t Ab = sbase + OFF_AHI;
    const uint32_t Bb = sbase + OFF_BHI;
#pragma unroll
    for (int ks = 0; ks < 8; ++ks) {
        uint32_t afr[4][4], bfr[4][2];
#pragma unroll
        for (int mt = 0; mt < 4; ++mt)
            ldmx4(afr[mt], Ab + aoff[mt]
                           + (uint32_t)(((2 * ks + lh) ^ a7[mt]) << 4));
#pragma unroll
        for (int q = 0; q < 2; ++q) {
            uint32_t tmp[4];
            ldmx4(tmp, Bb + boff[q]
                       + (uint32_t)(((2 * ks + lh) ^ b7[q]) << 4));
            bfr[2 * q][0] = tmp[0]; bfr[2 * q][1] = tmp[2];
            bfr[2 * q + 1][0] = tmp[1]; bfr[2 * q + 1][1] = tmp[3];
        }
#pragma unroll
        for (int mt = 0; mt < 4; ++mt)
#pragma unroll
            for (int nt = 0; nt < 4; ++nt)
                mma16816(acc[mt][nt], afr[mt], bfr[nt][0], bfr[nt][1]);
    }

    // ---- epilogue: top-2 (strict-upper blocks skip the i<j predicates) ----
    float v1 = -FLT_MAX, v2 = -FLT_MAX; int i1 = -1, i2 = -1;
    const int grow = rowBase + wm * 64 + (lane >> 2);
    const int gcol = colBase + wn * 32 + (lane & 3) * 2;
    if (bx > by) {
#pragma unroll
        for (int mt = 0; mt < 4; ++mt)
#pragma unroll
            for (int nt = 0; nt < 4; ++nt) {
                int gi = grow + mt * 16, gj = gcol + nt * 8;
                ins2(v1, i1, v2, i2, acc[mt][nt][0], gi * N + gj);
                ins2(v1, i1, v2, i2, acc[mt][nt][1], gi * N + gj + 1);
                ins2(v1, i1, v2, i2, acc[mt][nt][2], (gi + 8) * N + gj);
                ins2(v1, i1, v2, i2, acc[mt][nt][3], (gi + 8) * N + gj + 1);
            }
    } else {
#pragma unroll
        for (int mt = 0; mt < 4; ++mt)
#pragma unroll
            for (int nt = 0; nt < 4; ++nt) {
                int gi = grow + mt * 16, gj = gcol + nt * 8;
                if (gi < gj)         ins2(v1, i1, v2, i2, acc[mt][nt][0], gi * N + gj);
                if (gi < gj + 1)     ins2(v1, i1, v2, i2, acc[mt][nt][1], gi * N + gj + 1);
                if (gi + 8 < gj)     ins2(v1, i1, v2, i2, acc[mt][nt][2], (gi + 8) * N + gj);
                if (gi + 8 < gj + 1) ins2(v1, i1, v2, i2, acc[mt][nt][3], (gi + 8) * N + gj + 1);
            }
    }

    // ---- block tree-reduce of 256 top-2 records ----
    __shared__ float sV[512];
    __shared__ int   sI[512];
    sV[2 * tid] = v1; sI[2 * tid] = i1;
    sV[2 * tid + 1] = v2; sI[2 * tid + 1] = i2;
    __syncthreads();
    for (int s = 128; s > 0; s >>= 1) {
        if (tid < s) {
            int o = 2 * (tid + s);
            ins2(v1, i1, v2, i2, sV[o], sI[o]);
            ins2(v1, i1, v2, i2, sV[o + 1], sI[o + 1]);
            sV[2 * tid] = v1; sI[2 * tid] = i1;
            sV[2 * tid + 1] = v2; sI[2 * tid + 1] = i2;
        }
        __syncthreads();
    }
    if (tid == 0) {
        g_blkV[bid * 2] = v1;     g_blkI[bid * 2] = i1;
        g_blkV[bid * 2 + 1] = v2; g_blkI[bid * 2 + 1] = i2;
    }
}

// Kernel 3a: top-8 screened candidates -> exact fp32 recompute -> exact top-2.
__global__ void cand_kernel(const float* __restrict__ x) {
    extern __shared__ char csm[];
    float* cv = (float*)csm;                       // 8192 floats
    int*   ci = (int*)(csm + NT * NT * 2 * 4);     // 8192 ints
    __shared__ float rv[256];
    __shared__ int   ri[256];
    __shared__ float candV[NCAND];
    __shared__ int   candI[NCAND];
    __shared__ float exactV[NCAND];
    const int t = threadIdx.x;
    const int M = NT * NT * 2;

    for (int i = t; i < M; i += 256) { cv[i] = g_blkV[i]; ci[i] = g_blkI[i]; }
    __syncthreads();

    // 8 rounds of masked argmax.
    for (int c = 0; c < NCAND; ++c) {
        float bv = -FLT_MAX; int bi = -1;
        for (int i = t; i < M; i += 256) {
            float v = cv[i];
            if (v > bv) { bv = v; bi = i; }
        }
        rv[t] = bv; ri[t] = bi;
        __syncthreads();
        for (int s = 128; s > 0; s >>= 1) {
            if (t < s && rv[t + s] > rv[t]) { rv[t] = rv[t + s]; ri[t] = ri[t + s]; }
            __syncthreads();
        }
        if (t == 0) {
            candV[c] = rv[0];
            candI[c] = (ri[0] >= 0) ? ci[ri[0]] : -1;
            if (ri[0] >= 0) cv[ri[0]] = -FLT_MAX;  // mask
        }
        __syncthreads();
    }

    // Exact fp32 recompute: warp w handles candidate w.
    const int wid = t >> 5, lane = t & 31;
    if (wid < NCAND) {
        int idx = candI[wid];
        float s = -FLT_MAX;
        if (idx >= 0) {
            int gi = idx >> 13, gj = idx & (N - 1);
            const float* a = x + (size_t)gi * D;
            const float* b = x + (size_t)gj * D;
            s = 0.f;
#pragma unroll
            for (int k = lane; k < D; k += 32) s = fmaf(a[k], b[k], s);
#pragma unroll
            for (int o = 16; o; o >>= 1) s += __shfl_xor_sync(0xffffffffu, s, o);
        }
        if (lane == 0) exactV[wid] = s;
    }
    __syncthreads();

    if (t == 0) {
        float v1 = -FLT_MAX, v2 = -FLT_MAX; int i1 = -1, i2 = -1;
#pragma unroll
        for (int c = 0; c < NCAND; ++c) ins2(v1, i1, v2, i2, exactV[c], candI[c]);
        g_topV[0] = v1; g_topV[1] = v2; g_topI[0] = i1;
    }
}

// Kernel 3b: per-block partial ratio sums (16 blocks x 256 threads, 1 p each).
__global__ void ratio_kernel() {
    __shared__ double sD[256];
    const int t = threadIdx.x;
    const int p = blockIdx.x * 256 + t;
    const float V1 = g_topV[0], V2 = g_topV[1];
    const int   I1 = g_topI[0];

    int sf = p * N + p + 1;
    float v = (I1 == sf) ? V2 : V1;
    sD[t] = (double)v / (double)g_self[p];
    __syncthreads();
    for (int s = 128; s > 0; s >>= 1) {
        if (t < s) sD[t] += sD[t + s];
        __syncthreads();
    }
    if (t == 0) g_part[blockIdx.x] = sD[0];
}

// Kernel 3c: deterministic combine.
__global__ void combine_kernel(float* __restrict__ out) {
    double s = 0.0;
#pragma unroll
    for (int i = 0; i < 16; ++i) s += g_part[i];
    out[0] = (float)(s / (double)P);
}

extern "C" void kernel_launch(void* const* d_in, const int* in_sizes, int n_in,
                              void* d_out, int out_size) {
    const float* x = (const float*)d_in[0];
    float* out = (float*)d_out;

    cudaFuncSetAttribute(gram_hmma_kernel,
                         cudaFuncAttributeMaxDynamicSharedMemorySize, DSMEM_TOTAL);
    cudaFuncSetAttribute(cand_kernel,
                         cudaFuncAttributeMaxDynamicSharedMemorySize, CAND_SMEM);

    convert_kernel<<<(N * D) / 256, 256>>>(x);
    self_kernel<<<P / 8, 256>>>(x);
    dim3 g(NT, NT);
    gram_hmma_kernel<<<g, 256, DSMEM_TOTAL>>>();
    cand_kernel<<<1, 256, CAND_SMEM>>>(x);
    ratio_kernel<<<16, 256>>>();
    combine_kernel<<<1, 1>>>(out);
}